// round 2
// baseline (speedup 1.0000x reference)
#include <cuda_runtime.h>
#include <cuda_bf16.h>
#include <math.h>
#include <stdint.h>

// Problem: x1 [B=32, Lq=32, D=128] f32, x2 [B=32, N=100, Ld=512, D=128] f32,
// x1_mask [B, Lq], x2_mask [B, N, Ld]. Output [B, N] f32:
//   out[b,n] = sum_q max_l dot(l2norm(x1[b,q]) * m1, l2norm(x2[b,n,l]) * m2)

#define B_ 32
#define LQ 32
#define N_ 100
#define LD 512
#define D_ 128

// Normalized x1 in bf16, [B][Lq][D]
__device__ __nv_bfloat16 g_x1n[B_ * LQ * D_];

// ---------------- Kernel A: normalize x1 ----------------
__global__ void norm_x1_kernel(const float* __restrict__ x1,
                               const float* __restrict__ x1_mask) {
    int row = blockIdx.x * (blockDim.x >> 5) + (threadIdx.x >> 5);  // b*32+q
    int lane = threadIdx.x & 31;
    if (row >= B_ * LQ) return;
    const float4 v = ((const float4*)(x1 + (size_t)row * D_))[lane];
    float ss = v.x * v.x + v.y * v.y + v.z * v.z + v.w * v.w;
    #pragma unroll
    for (int o = 16; o > 0; o >>= 1) ss += __shfl_xor_sync(0xffffffffu, ss, o);
    float inv = x1_mask[row] / fmaxf(sqrtf(ss), 1e-12f);
    __nv_bfloat162* dst = (__nv_bfloat162*)(g_x1n + (size_t)row * D_ + lane * 4);
    dst[0] = __floats2bfloat162_rn(v.x * inv, v.y * inv);
    dst[1] = __floats2bfloat162_rn(v.z * inv, v.w * inv);
}

// ---------------- bf16 MMA m16n8k16 ----------------
__device__ __forceinline__ void mma_bf16(float* c,
                                         uint32_t a0, uint32_t a1, uint32_t a2, uint32_t a3,
                                         uint32_t b0, uint32_t b1) {
    asm volatile(
        "mma.sync.aligned.m16n8k16.row.col.f32.bf16.bf16.f32 "
        "{%0,%1,%2,%3}, {%4,%5,%6,%7}, {%8,%9}, {%0,%1,%2,%3};\n"
        : "+f"(c[0]), "+f"(c[1]), "+f"(c[2]), "+f"(c[3])
        : "r"(a0), "r"(a1), "r"(a2), "r"(a3), "r"(b0), "r"(b1));
}

// ---------------- Kernel B: fused normalize(x2) + MaxSim ----------------
// Grid: (N_, B_). Block: 256 threads (8 warps).
// Each CTA handles one (b, n); loops over 8 l-tiles of 64 rows.
// Warp w: M-tile (l) = w&3 within the 64-row tile, N-tiles (q) = {0,1} if w<4 else {2,3}.
#define LTILE 64
#define SAPAD 136  // 272B row stride -> frag-load bank = (4g+t+8k)%32, conflict-free

__global__ __launch_bounds__(256, 4) void maxsim_kernel(const float* __restrict__ x2,
                                                        const float* __restrict__ x2_mask,
                                                        float* __restrict__ out) {
    __shared__ __nv_bfloat16 sA[LTILE][SAPAD];  // x2 tile, row = l, col = k
    __shared__ __nv_bfloat16 sB[LQ][SAPAD];     // x1, row = q, col = k
    __shared__ float sred[8][32];               // per-warp per-q running max

    const int n = blockIdx.x;
    const int b = blockIdx.y;
    const int tid = threadIdx.x;
    const int warp = tid >> 5;
    const int lane = tid & 31;

    // Load normalized x1 (bf16) into sB (ordered before first MMA read by the
    // post-store __syncthreads() inside the first loop iteration)
    {
        const uint32_t* src = (const uint32_t*)(g_x1n + (size_t)b * LQ * D_);
        #pragma unroll
        for (int i = tid; i < LQ * (D_ / 2); i += 256) {
            int q = i >> 6;          // 64 u32 per row
            int c = i & 63;
            ((uint32_t*)&sB[q][0])[c] = src[q * 64 + c];
        }
    }

    const float* x2base = x2 + ((size_t)b * N_ + n) * (size_t)LD * D_;
    const float* mbase = x2_mask + ((size_t)b * N_ + n) * LD;

    const int row_in_tile = tid >> 2;  // 0..63: one x2 row per 4 threads
    const int quad = tid & 3;

    const int mt = warp & 3;           // m-tile within 64-row l tile
    const int nt0 = (warp >> 2) * 2;   // first of two n-tiles (q groups of 8)
    const int g = lane >> 2;           // fragment group row
    const int t = lane & 3;            // fragment quad col

    float qmax[4] = {-INFINITY, -INFINITY, -INFINITY, -INFINITY};

    for (int lt = 0; lt < LD / LTILE; ++lt) {
        // ---- Load 64 x2 rows (f32), compute row norms, store bf16 to sA ----
        const int l = lt * LTILE + row_in_tile;
        const float4* src = (const float4*)(x2base + (size_t)l * D_);
        float4 v[8];
        float ss = 0.f;
        #pragma unroll
        for (int i = 0; i < 8; ++i) {
            v[i] = src[quad * 8 + i];
            ss += v[i].x * v[i].x + v[i].y * v[i].y + v[i].z * v[i].z + v[i].w * v[i].w;
        }
        ss += __shfl_xor_sync(0xffffffffu, ss, 1);
        ss += __shfl_xor_sync(0xffffffffu, ss, 2);
        const float inv = mbase[l] / fmaxf(sqrtf(ss), 1e-12f);

        __syncthreads();  // previous tile's MMA reads done (and sB writes visible)
        #pragma unroll
        for (int i = 0; i < 8; ++i) {
            __nv_bfloat162* d = (__nv_bfloat162*)&sA[row_in_tile][quad * 32 + i * 4];
            d[0] = __floats2bfloat162_rn(v[i].x * inv, v[i].y * inv);
            d[1] = __floats2bfloat162_rn(v[i].z * inv, v[i].w * inv);
        }
        __syncthreads();

        // ---- MMA: sim tile [16 l] x [16 q] per warp ----
        float c0[4] = {0.f, 0.f, 0.f, 0.f};
        float c1[4] = {0.f, 0.f, 0.f, 0.f};
        #pragma unroll
        for (int k = 0; k < 8; ++k) {
            const int k0 = k * 16;
            uint32_t a0 = *(const uint32_t*)&sA[mt * 16 + g][k0 + 2 * t];
            uint32_t a1 = *(const uint32_t*)&sA[mt * 16 + g + 8][k0 + 2 * t];
            uint32_t a2 = *(const uint32_t*)&sA[mt * 16 + g][k0 + 2 * t + 8];
            uint32_t a3 = *(const uint32_t*)&sA[mt * 16 + g + 8][k0 + 2 * t + 8];
            uint32_t b0 = *(const uint32_t*)&sB[nt0 * 8 + g][k0 + 2 * t];
            uint32_t b1 = *(const uint32_t*)&sB[nt0 * 8 + g][k0 + 2 * t + 8];
            mma_bf16(c0, a0, a1, a2, a3, b0, b1);
            uint32_t b2 = *(const uint32_t*)&sB[(nt0 + 1) * 8 + g][k0 + 2 * t];
            uint32_t b3 = *(const uint32_t*)&sB[(nt0 + 1) * 8 + g][k0 + 2 * t + 8];
            mma_bf16(c1, a0, a1, a2, a3, b2, b3);
        }

        // ---- fold into running per-q max (max over this warp's 16 l-rows) ----
        float m0 = fmaxf(c0[0], c0[2]);  // col 2t
        float m1 = fmaxf(c0[1], c0[3]);  // col 2t+1
        float m2 = fmaxf(c1[0], c1[2]);
        float m3 = fmaxf(c1[1], c1[3]);
        #pragma unroll
        for (int o = 4; o < 32; o <<= 1) {
            m0 = fmaxf(m0, __shfl_xor_sync(0xffffffffu, m0, o));
            m1 = fmaxf(m1, __shfl_xor_sync(0xffffffffu, m1, o));
            m2 = fmaxf(m2, __shfl_xor_sync(0xffffffffu, m2, o));
            m3 = fmaxf(m3, __shfl_xor_sync(0xffffffffu, m3, o));
        }
        qmax[0] = fmaxf(qmax[0], m0);
        qmax[1] = fmaxf(qmax[1], m1);
        qmax[2] = fmaxf(qmax[2], m2);
        qmax[3] = fmaxf(qmax[3], m3);
    }

    // ---- Epilogue: cross-warp max, then sum over q ----
    if (lane < 4) {  // lanes 0..3 (g=0) hold cols 2t, 2t+1 of each n-tile
        sred[warp][nt0 * 8 + 2 * lane] = qmax[0];
        sred[warp][nt0 * 8 + 2 * lane + 1] = qmax[1];
        sred[warp][(nt0 + 1) * 8 + 2 * lane] = qmax[2];
        sred[warp][(nt0 + 1) * 8 + 2 * lane + 1] = qmax[3];
    }
    __syncthreads();
    if (tid < 32) {
        const int q = tid;
        const int wb = (q >= 16) ? 4 : 0;  // warps covering this q's n-tile
        float m = fmaxf(fmaxf(sred[wb][q], sred[wb + 1][q]),
                        fmaxf(sred[wb + 2][q], sred[wb + 3][q]));
        #pragma unroll
        for (int o = 16; o > 0; o >>= 1) m += __shfl_xor_sync(0xffffffffu, m, o);
        if (q == 0) out[(size_t)b * N_ + n] = m;
    }
}

// ---------------- Launch ----------------
extern "C" void kernel_launch(void* const* d_in, const int* in_sizes, int n_in,
                              void* d_out, int out_size) {
    const float* x1 = (const float*)d_in[0];
    const float* x2 = (const float*)d_in[1];
    const float* x1_mask = (const float*)d_in[2];
    const float* x2_mask = (const float*)d_in[3];
    float* out = (float*)d_out;

    norm_x1_kernel<<<(B_ * LQ) / 8, 256>>>(x1, x1_mask);
    dim3 grid(N_, B_);
    maxsim_kernel<<<grid, 256>>>(x2, x2_mask, out);
}

// round 8
// speedup vs baseline: 1.1136x; 1.1136x over previous
#include <cuda_runtime.h>
#include <cuda_bf16.h>
#include <math.h>
#include <stdint.h>
#include <string.h>

// Problem: x1 [B=32, Lq=32, D=128] f32, x2 [B=32, N=100, Ld=512, D=128] f32,
// x1_mask [B, Lq], x2_mask [B, N, Ld]. Output [B, N] f32:
//   out[b,n] = sum_q max_l dot(l2norm(x1[b,q]) * m1, l2norm(x2[b,n,l]) * m2)

#define B_ 32
#define LQ 32
#define N_ 100
#define LD 512
#define D_ 128

// Normalized x1 in bf16, [B][Lq][D]
__device__ __nv_bfloat16 g_x1n[B_ * LQ * D_];

__device__ __forceinline__ uint32_t bf2u(float a, float b) {
    __nv_bfloat162 h = __floats2bfloat162_rn(a, b);
    uint32_t u;
    memcpy(&u, &h, 4);
    return u;
}

// ---------------- Kernel A: normalize x1 ----------------
__global__ void norm_x1_kernel(const float* __restrict__ x1,
                               const float* __restrict__ x1_mask) {
    int row = blockIdx.x * (blockDim.x >> 5) + (threadIdx.x >> 5);  // b*32+q
    int lane = threadIdx.x & 31;
    if (row >= B_ * LQ) return;
    const float4 v = ((const float4*)(x1 + (size_t)row * D_))[lane];
    float ss = v.x * v.x + v.y * v.y + v.z * v.z + v.w * v.w;
    #pragma unroll
    for (int o = 16; o > 0; o >>= 1) ss += __shfl_xor_sync(0xffffffffu, ss, o);
    float inv = x1_mask[row] / fmaxf(sqrtf(ss), 1e-12f);
    uint32_t* dst = (uint32_t*)(g_x1n + (size_t)row * D_ + lane * 4);
    dst[0] = bf2u(v.x * inv, v.y * inv);
    dst[1] = bf2u(v.z * inv, v.w * inv);
}

// ---------------- bf16 MMA m16n8k16 ----------------
__device__ __forceinline__ void mma_bf16(float* c,
                                         uint32_t a0, uint32_t a1, uint32_t a2, uint32_t a3,
                                         uint32_t b0, uint32_t b1) {
    asm volatile(
        "mma.sync.aligned.m16n8k16.row.col.f32.bf16.bf16.f32 "
        "{%0,%1,%2,%3}, {%4,%5,%6,%7}, {%8,%9}, {%0,%1,%2,%3};\n"
        : "+f"(c[0]), "+f"(c[1]), "+f"(c[2]), "+f"(c[3])
        : "r"(a0), "r"(a1), "r"(a2), "r"(a3), "r"(b0), "r"(b1));
}

__device__ __forceinline__ void ldsm_x4(uint32_t& r0, uint32_t& r1,
                                        uint32_t& r2, uint32_t& r3, uint32_t addr) {
    asm volatile("ldmatrix.sync.aligned.m8n8.x4.shared.b16 {%0,%1,%2,%3}, [%4];\n"
                 : "=r"(r0), "=r"(r1), "=r"(r2), "=r"(r3) : "r"(addr));
}

// ---------------- Kernel B: fused normalize(x2) + MaxSim ----------------
// Grid: (N_, B_). Block: 256 threads (8 warps).
// Each CTA handles one (b, n); loops over 8 l-tiles of 64 rows.
// Warp w: M-tile (l) = w&3, N-tiles (q) = {0,1} if w<4 else {2,3}.
#define LTILE 64
#define SAPAD 136  // 272B row stride -> ldmatrix phase quads r*16 mod 128: conflict-free

__global__ __launch_bounds__(256, 4) void maxsim_kernel(const float* __restrict__ x2,
                                                        const float* __restrict__ x2_mask,
                                                        float* __restrict__ out) {
    __shared__ __nv_bfloat16 sA[LTILE][SAPAD];  // x2 tile, row = l, col = k
    __shared__ __nv_bfloat16 sB[LQ][SAPAD];     // x1, row = q, col = k
    __shared__ float sred[8][32];               // per-warp per-q max

    const int n = blockIdx.x;
    const int b = blockIdx.y;
    const int tid = threadIdx.x;
    const int warp = tid >> 5;
    const int lane = tid & 31;

    // Load normalized x1 (bf16) into sB (ordered before first MMA read by the
    // post-store __syncthreads() inside the first loop iteration)
    {
        const uint32_t* src = (const uint32_t*)(g_x1n + (size_t)b * LQ * D_);
        #pragma unroll
        for (int i = tid; i < LQ * (D_ / 2); i += 256) {
            int q = i >> 6;          // 64 u32 per row
            int c = i & 63;
            ((uint32_t*)&sB[q][0])[c] = src[q * 64 + c];
        }
    }

    const float* x2base = x2 + ((size_t)b * N_ + n) * (size_t)LD * D_;
    const float* mbase = x2_mask + ((size_t)b * N_ + n) * LD;

    const int row_in_tile = tid >> 2;  // 0..63: one x2 row per 4 threads
    const int quad = tid & 3;

    const int mt = warp & 3;           // m-tile within 64-row l tile
    const int nt0 = (warp >> 2) * 2;   // first of two n-tiles (q groups of 8)

    // ldmatrix lane addresses
    // A (16x16): mat0=(r0-7,k0-7) mat1=(r8-15,k0-7) mat2=(r0-7,k8-15) mat3=(r8-15,k8-15)
    const int laneA_row = mt * 16 + ((lane >> 3) & 1) * 8 + (lane & 7);
    const uint32_t aBase =
        (uint32_t)__cvta_generic_to_shared(&sA[laneA_row][0]) + (lane >> 4) * 16;
    // B (2 n-tiles x 16k): mat0=(nt0,k0-7) mat1=(nt0,k8-15) mat2=(nt0+1,k0-7) mat3=(nt0+1,k8-15)
    const int laneB_row = nt0 * 8 + ((lane >> 4) & 1) * 8 + (lane & 7);
    const uint32_t bBase =
        (uint32_t)__cvta_generic_to_shared(&sB[laneB_row][0]) + ((lane >> 3) & 1) * 16;

    float qc0[4] = {-INFINITY, -INFINITY, -INFINITY, -INFINITY};
    float qc1[4] = {-INFINITY, -INFINITY, -INFINITY, -INFINITY};

    for (int lt = 0; lt < LD / LTILE; ++lt) {
        // ---- Load 64 x2 rows (f32), compute row norms, store bf16 to sA ----
        const int l = lt * LTILE + row_in_tile;
        const float4* src = (const float4*)(x2base + (size_t)l * D_);
        float4 v[8];
        float ss = 0.f;
        #pragma unroll
        for (int i = 0; i < 8; ++i) {
            v[i] = src[quad * 8 + i];
            ss += v[i].x * v[i].x + v[i].y * v[i].y + v[i].z * v[i].z + v[i].w * v[i].w;
        }
        ss += __shfl_xor_sync(0xffffffffu, ss, 1);
        ss += __shfl_xor_sync(0xffffffffu, ss, 2);
        const float inv = mbase[l] / fmaxf(sqrtf(ss), 1e-12f);

        __syncthreads();  // previous tile's MMA reads done (and sB writes visible)
        #pragma unroll
        for (int j = 0; j < 4; ++j) {
            uint4 u;
            u.x = bf2u(v[2 * j].x * inv, v[2 * j].y * inv);
            u.y = bf2u(v[2 * j].z * inv, v[2 * j].w * inv);
            u.z = bf2u(v[2 * j + 1].x * inv, v[2 * j + 1].y * inv);
            u.w = bf2u(v[2 * j + 1].z * inv, v[2 * j + 1].w * inv);
            *(uint4*)&sA[row_in_tile][quad * 32 + j * 8] = u;
        }
        __syncthreads();

        // ---- MMA: sim tile [16 l] x [16 q] per warp ----
        float c0[4] = {0.f, 0.f, 0.f, 0.f};
        float c1[4] = {0.f, 0.f, 0.f, 0.f};
        #pragma unroll
        for (int k = 0; k < 8; ++k) {
            uint32_t a0, a1, a2, a3, b0, b1, b2, b3;
            ldsm_x4(a0, a1, a2, a3, aBase + k * 32);
            ldsm_x4(b0, b1, b2, b3, bBase + k * 32);
            mma_bf16(c0, a0, a1, a2, a3, b0, b1);
            mma_bf16(c1, a0, a1, a2, a3, b2, b3);
        }

        // ---- running elementwise max (cross-lane fold deferred to epilogue) ----
        #pragma unroll
        for (int i = 0; i < 4; ++i) {
            qc0[i] = fmaxf(qc0[i], c0[i]);
            qc1[i] = fmaxf(qc1[i], c1[i]);
        }
    }

    // ---- One-time fold: max over this warp's 16 l-rows ----
    float m0 = fmaxf(qc0[0], qc0[2]);  // col 2t
    float m1 = fmaxf(qc0[1], qc0[3]);  // col 2t+1
    float m2 = fmaxf(qc1[0], qc1[2]);
    float m3 = fmaxf(qc1[1], qc1[3]);
    #pragma unroll
    for (int o = 4; o < 32; o <<= 1) {
        m0 = fmaxf(m0, __shfl_xor_sync(0xffffffffu, m0, o));
        m1 = fmaxf(m1, __shfl_xor_sync(0xffffffffu, m1, o));
        m2 = fmaxf(m2, __shfl_xor_sync(0xffffffffu, m2, o));
        m3 = fmaxf(m3, __shfl_xor_sync(0xffffffffu, m3, o));
    }

    // ---- Epilogue: cross-warp max, then sum over q ----
    if (lane < 4) {  // lanes 0..3 (g=0) hold cols 2t, 2t+1 of each n-tile
        sred[warp][nt0 * 8 + 2 * lane] = m0;
        sred[warp][nt0 * 8 + 2 * lane + 1] = m1;
        sred[warp][(nt0 + 1) * 8 + 2 * lane] = m2;
        sred[warp][(nt0 + 1) * 8 + 2 * lane + 1] = m3;
    }
    __syncthreads();
    if (tid < 32) {
        const int q = tid;
        const int wb = (q >= 16) ? 4 : 0;  // warps covering this q's n-tile
        float m = fmaxf(fmaxf(sred[wb][q], sred[wb + 1][q]),
                        fmaxf(sred[wb + 2][q], sred[wb + 3][q]));
        #pragma unroll
        for (int o = 16; o > 0; o >>= 1) m += __shfl_xor_sync(0xffffffffu, m, o);
        if (q == 0) out[(size_t)b * N_ + n] = m;
    }
}

// ---------------- Launch ----------------
extern "C" void kernel_launch(void* const* d_in, const int* in_sizes, int n_in,
                              void* d_out, int out_size) {
    const float* x1 = (const float*)d_in[0];
    const float* x2 = (const float*)d_in[1];
    const float* x1_mask = (const float*)d_in[2];
    const float* x2_mask = (const float*)d_in[3];
    float* out = (float*)d_out;

    norm_x1_kernel<<<(B_ * LQ) / 8, 256>>>(x1, x1_mask);
    dim3 grid(N_, B_);
    maxsim_kernel<<<grid, 256>>>(x2, x2_mask, out);
}

// round 13
// speedup vs baseline: 2.1080x; 1.8929x over previous
#include <cuda_runtime.h>
#include <cuda_bf16.h>
#include <math.h>
#include <stdint.h>
#include <string.h>

// Problem: x1 [B=32, Lq=32, D=128] f32, x2 [B=32, N=100, Ld=512, D=128] f32,
// x1_mask [B, Lq], x2_mask [B, N, Ld]. Output [B, N] f32:
//   out[b,n] = sum_q max_l dot(l2norm(x1[b,q]) * m1, l2norm(x2[b,n,l]) * m2)

#define B_ 32
#define LQ 32
#define N_ 100
#define LD 512
#define D_ 128

// Normalized x1 in bf16, [B][Lq][D]
__device__ __nv_bfloat16 g_x1n[B_ * LQ * D_];

__device__ __forceinline__ uint32_t bf2u(float a, float b) {
    __nv_bfloat162 h = __floats2bfloat162_rn(a, b);
    uint32_t u;
    memcpy(&u, &h, 4);
    return u;
}

// ---------------- Kernel A: normalize x1 ----------------
__global__ void norm_x1_kernel(const float* __restrict__ x1,
                               const float* __restrict__ x1_mask) {
    int row = blockIdx.x * (blockDim.x >> 5) + (threadIdx.x >> 5);  // b*32+q
    int lane = threadIdx.x & 31;
    if (row >= B_ * LQ) return;
    const float4 v = ((const float4*)(x1 + (size_t)row * D_))[lane];
    float ss = v.x * v.x + v.y * v.y + v.z * v.z + v.w * v.w;
    #pragma unroll
    for (int o = 16; o > 0; o >>= 1) ss += __shfl_xor_sync(0xffffffffu, ss, o);
    float inv = x1_mask[row] / fmaxf(sqrtf(ss), 1e-12f);
    uint32_t* dst = (uint32_t*)(g_x1n + (size_t)row * D_ + lane * 4);
    dst[0] = bf2u(v.x * inv, v.y * inv);
    dst[1] = bf2u(v.z * inv, v.w * inv);
}

// ---------------- bf16 MMA m16n8k16 ----------------
__device__ __forceinline__ void mma_bf16(float* c,
                                         uint32_t a0, uint32_t a1, uint32_t a2, uint32_t a3,
                                         uint32_t b0, uint32_t b1) {
    asm volatile(
        "mma.sync.aligned.m16n8k16.row.col.f32.bf16.bf16.f32 "
        "{%0,%1,%2,%3}, {%4,%5,%6,%7}, {%8,%9}, {%0,%1,%2,%3};\n"
        : "+f"(c[0]), "+f"(c[1]), "+f"(c[2]), "+f"(c[3])
        : "r"(a0), "r"(a1), "r"(a2), "r"(a3), "r"(b0), "r"(b1));
}

__device__ __forceinline__ void ldsm_x4(uint32_t& r0, uint32_t& r1,
                                        uint32_t& r2, uint32_t& r3, uint32_t addr) {
    asm volatile("ldmatrix.sync.aligned.m8n8.x4.shared.b16 {%0,%1,%2,%3}, [%4];\n"
                 : "=r"(r0), "=r"(r1), "=r"(r2), "=r"(r3) : "r"(addr));
}

// ---------------- Kernel B: fused normalize(x2) + MaxSim ----------------
// Grid: (N_, B_). Block: 256 threads (8 warps).
// Each CTA handles one (b, n); loops over 8 l-tiles of 64 rows.
// Warp w: M-tile (l) = w&3, N-tiles (q) = {0,1} if w<4 else {2,3}.
#define LTILE 64
#define SAPAD 136  // 272B row stride -> ldmatrix phase quads r*16 mod 128: conflict-free

__global__ __launch_bounds__(256, 4) void maxsim_kernel(const float* __restrict__ x2,
                                                        const float* __restrict__ x2_mask,
                                                        float* __restrict__ out) {
    __shared__ __nv_bfloat16 sA[LTILE][SAPAD];  // x2 tile, row = l, col = k
    __shared__ __nv_bfloat16 sB[LQ][SAPAD];     // x1, row = q, col = k
    __shared__ float sred[8][32];               // per-warp per-q max

    const int n = blockIdx.x;
    const int b = blockIdx.y;
    const int tid = threadIdx.x;
    const int warp = tid >> 5;
    const int lane = tid & 31;

    // Load normalized x1 (bf16) into sB (ordered before first MMA read by the
    // post-store __syncthreads() inside the first loop iteration)
    {
        const uint32_t* src = (const uint32_t*)(g_x1n + (size_t)b * LQ * D_);
        #pragma unroll
        for (int i = tid; i < LQ * (D_ / 2); i += 256) {
            int q = i >> 6;          // 64 u32 per row
            int c = i & 63;
            ((uint32_t*)&sB[q][0])[c] = src[q * 64 + c];
        }
    }

    const float* x2base = x2 + ((size_t)b * N_ + n) * (size_t)LD * D_;
    const float* mbase = x2_mask + ((size_t)b * N_ + n) * LD;

    const int row_in_tile = tid >> 2;  // 0..63: one x2 row per 4 threads
    const int quad = tid & 3;

    const int mt = warp & 3;           // m-tile within 64-row l tile
    const int nt0 = (warp >> 2) * 2;   // first of two n-tiles (q groups of 8)

    // ldmatrix lane addresses
    // A (16x16): mat0=(r0-7,k0-7) mat1=(r8-15,k0-7) mat2=(r0-7,k8-15) mat3=(r8-15,k8-15)
    const int laneA_row = mt * 16 + ((lane >> 3) & 1) * 8 + (lane & 7);
    const uint32_t aBase =
        (uint32_t)__cvta_generic_to_shared(&sA[laneA_row][0]) + (lane >> 4) * 16;
    // B (2 n-tiles x 16k): mat0=(nt0,k0-7) mat1=(nt0,k8-15) mat2=(nt0+1,k0-7) mat3=(nt0+1,k8-15)
    const int laneB_row = nt0 * 8 + ((lane >> 4) & 1) * 8 + (lane & 7);
    const uint32_t bBase =
        (uint32_t)__cvta_generic_to_shared(&sB[laneB_row][0]) + ((lane >> 3) & 1) * 16;

    float qc0[4] = {-INFINITY, -INFINITY, -INFINITY, -INFINITY};
    float qc1[4] = {-INFINITY, -INFINITY, -INFINITY, -INFINITY};

    for (int lt = 0; lt < LD / LTILE; ++lt) {
        // ---- Load 64 x2 rows (f32), sector-coherent: thread (r,q) reads float4
        // pairs {m*8+q*2, m*8+q*2+1}. Per LDG the 4 quads of a row hit the SAME
        // 128B sector (offsets q*32), so each warp instr = 8 sectors, not 32. ----
        const int l = lt * LTILE + row_in_tile;
        const float4* src = (const float4*)(x2base + (size_t)l * D_);
        float4 v[8];
        float ss = 0.f;
        #pragma unroll
        for (int m = 0; m < 4; ++m) {
            v[2 * m] = src[m * 8 + quad * 2];
            v[2 * m + 1] = src[m * 8 + quad * 2 + 1];
        }
        #pragma unroll
        for (int i = 0; i < 8; ++i)
            ss += v[i].x * v[i].x + v[i].y * v[i].y + v[i].z * v[i].z + v[i].w * v[i].w;
        ss += __shfl_xor_sync(0xffffffffu, ss, 1);
        ss += __shfl_xor_sync(0xffffffffu, ss, 2);
        const float inv = mbase[l] / fmaxf(sqrtf(ss), 1e-12f);

        __syncthreads();  // previous tile's MMA reads done (and sB writes visible)
        // v[2m], v[2m+1] cover bf16 element cols [m*32+q*8, m*32+q*8+8): one STS.128.
        // Bank slot (r+q) mod 8 -> 4-phase minimum, conflict-free.
        #pragma unroll
        for (int m = 0; m < 4; ++m) {
            uint4 u;
            u.x = bf2u(v[2 * m].x * inv, v[2 * m].y * inv);
            u.y = bf2u(v[2 * m].z * inv, v[2 * m].w * inv);
            u.z = bf2u(v[2 * m + 1].x * inv, v[2 * m + 1].y * inv);
            u.w = bf2u(v[2 * m + 1].z * inv, v[2 * m + 1].w * inv);
            *(uint4*)&sA[row_in_tile][m * 32 + quad * 8] = u;
        }
        __syncthreads();

        // ---- MMA: sim tile [16 l] x [16 q] per warp ----
        float c0[4] = {0.f, 0.f, 0.f, 0.f};
        float c1[4] = {0.f, 0.f, 0.f, 0.f};
        #pragma unroll
        for (int k = 0; k < 8; ++k) {
            uint32_t a0, a1, a2, a3, b0, b1, b2, b3;
            ldsm_x4(a0, a1, a2, a3, aBase + k * 32);
            ldsm_x4(b0, b1, b2, b3, bBase + k * 32);
            mma_bf16(c0, a0, a1, a2, a3, b0, b1);
            mma_bf16(c1, a0, a1, a2, a3, b2, b3);
        }

        // ---- running elementwise max (cross-lane fold deferred to epilogue) ----
        #pragma unroll
        for (int i = 0; i < 4; ++i) {
            qc0[i] = fmaxf(qc0[i], c0[i]);
            qc1[i] = fmaxf(qc1[i], c1[i]);
        }
    }

    // ---- One-time fold: max over this warp's 16 l-rows ----
    float m0 = fmaxf(qc0[0], qc0[2]);  // col 2t
    float m1 = fmaxf(qc0[1], qc0[3]);  // col 2t+1
    float m2 = fmaxf(qc1[0], qc1[2]);
    float m3 = fmaxf(qc1[1], qc1[3]);
    #pragma unroll
    for (int o = 4; o < 32; o <<= 1) {
        m0 = fmaxf(m0, __shfl_xor_sync(0xffffffffu, m0, o));
        m1 = fmaxf(m1, __shfl_xor_sync(0xffffffffu, m1, o));
        m2 = fmaxf(m2, __shfl_xor_sync(0xffffffffu, m2, o));
        m3 = fmaxf(m3, __shfl_xor_sync(0xffffffffu, m3, o));
    }

    // ---- Epilogue: cross-warp max, then sum over q ----
    if (lane < 4) {  // lanes 0..3 (g=0) hold cols 2t, 2t+1 of each n-tile
        sred[warp][nt0 * 8 + 2 * lane] = m0;
        sred[warp][nt0 * 8 + 2 * lane + 1] = m1;
        sred[warp][(nt0 + 1) * 8 + 2 * lane] = m2;
        sred[warp][(nt0 + 1) * 8 + 2 * lane + 1] = m3;
    }
    __syncthreads();
    if (tid < 32) {
        const int q = tid;
        const int wb = (q >= 16) ? 4 : 0;  // warps covering this q's n-tile
        float m = fmaxf(fmaxf(sred[wb][q], sred[wb + 1][q]),
                        fmaxf(sred[wb + 2][q], sred[wb + 3][q]));
        #pragma unroll
        for (int o = 16; o > 0; o >>= 1) m += __shfl_xor_sync(0xffffffffu, m, o);
        if (q == 0) out[(size_t)b * N_ + n] = m;
    }
}

// ---------------- Launch ----------------
extern "C" void kernel_launch(void* const* d_in, const int* in_sizes, int n_in,
                              void* d_out, int out_size) {
    const float* x1 = (const float*)d_in[0];
    const float* x2 = (const float*)d_in[1];
    const float* x1_mask = (const float*)d_in[2];
    const float* x2_mask = (const float*)d_in[3];
    float* out = (float*)d_out;

    norm_x1_kernel<<<(B_ * LQ) / 8, 256>>>(x1, x1_mask);
    dim3 grid(N_, B_);
    maxsim_kernel<<<grid, 256>>>(x2, x2_mask, out);
}